// round 1
// baseline (speedup 1.0000x reference)
#include <cuda_runtime.h>
#include <cstdint>

#define NN 60000
#define EE 240000
#define FIN 10
#define GG 512

// ---------------- scratch layout (floats) ----------------
// A1  : N*96   (h1 | U1(3x16) | V1 | x@root1)
// H2  : N*32   (g1 @ W_gcn2)
// UV2 : N*128  (U2(3x32) | V2)
// XR2 : N*32   (c1 @ root2)
// WA  : 960    (stageA fused weight [10,96])
// WC  : 2560   (stageC fused weight [16,160])
// -- zeroed region --
// AG1 : N*16, AC1 : N*16, AG2 : N*32, AC2 : N*32, POOL : G*64
constexpr int OFF_A1   = 0;
constexpr int OFF_H2   = OFF_A1  + NN * 96;
constexpr int OFF_UV2  = OFF_H2  + NN * 32;
constexpr int OFF_XR2  = OFF_UV2 + NN * 128;
constexpr int OFF_WA   = OFF_XR2 + NN * 32;
constexpr int OFF_WC   = OFF_WA  + 960;
constexpr int OFF_ZERO = OFF_WC  + 2560;
constexpr int OFF_AG1  = OFF_ZERO;
constexpr int OFF_AC1  = OFF_AG1 + NN * 16;
constexpr int OFF_AG2  = OFF_AC1 + NN * 16;
constexpr int OFF_AC2  = OFF_AG2 + NN * 32;
constexpr int OFF_POOL = OFF_AC2 + NN * 32;
constexpr int SCRATCH_TOTAL = OFF_POOL + GG * 64;
constexpr int ZERO_COUNT = SCRATCH_TOTAL - OFF_ZERO;

__device__ __align__(16) float d_scratch[SCRATCH_TOTAL];

// ---------------- helpers ----------------
__device__ __forceinline__ void red_add_v4(float* addr, float4 v) {
    asm volatile("red.global.add.v4.f32 [%0], {%1, %2, %3, %4};"
                 :: "l"(addr), "f"(v.x), "f"(v.y), "f"(v.z), "f"(v.w)
                 : "memory");
}

__device__ __forceinline__ float4 relu4(float4 v) {
    v.x = fmaxf(v.x, 0.f); v.y = fmaxf(v.y, 0.f);
    v.z = fmaxf(v.z, 0.f); v.w = fmaxf(v.w, 0.f);
    return v;
}

// ---------------- kernels ----------------
__global__ void zero_kernel() {
    int i = blockIdx.x * blockDim.x + threadIdx.x;
    float4* p = (float4*)(d_scratch + OFF_ZERO);
    if (i < ZERO_COUNT / 4) p[i] = make_float4(0.f, 0.f, 0.f, 0.f);
}

__global__ void prep_kernel(const float* __restrict__ Wg1,
                            const float* __restrict__ We1, const float* __restrict__ be1,
                            const float* __restrict__ root1,
                            const float* __restrict__ We2, const float* __restrict__ be2,
                            const float* __restrict__ root2) {
    int i = blockIdx.x * blockDim.x + threadIdx.x;
    if (i < 960) {                       // WA[f*96 + c], f in [0,10)
        int f = i / 96, c = i % 96;
        float v;
        if (c < 16)       v = Wg1[f * 16 + c];
        else if (c < 64)  { int s = (c - 16) >> 4, o = (c - 16) & 15; v = We1[s * 160 + f * 16 + o]; }
        else if (c < 80)  v = be1[f * 16 + (c - 64)];
        else              v = root1[f * 16 + (c - 80)];
        d_scratch[OFF_WA + i] = v;
    }
    int j = i - 960;
    if (j >= 0 && j < 2560) {            // WC[f*160 + c], f in [0,16)
        int f = j / 160, c = j % 160;
        float v;
        if (c < 96)       { int s = c / 32, o = c % 32; v = We2[s * 512 + f * 32 + o]; }
        else if (c < 128) v = be2[f * 32 + (c - 96)];
        else              v = root2[f * 32 + (c - 128)];
        d_scratch[OFF_WC + j] = v;
    }
}

// x[N,10] @ WA[10,96] -> A1[N,96]
__global__ void stageA_kernel(const float* __restrict__ x) {
    __shared__ float sWA[960];
    for (int i = threadIdx.x; i < 960; i += blockDim.x) sWA[i] = d_scratch[OFF_WA + i];
    __syncthreads();
    int idx = blockIdx.x * blockDim.x + threadIdx.x;
    if (idx >= NN * 96) return;
    int j = idx / 96, c = idx % 96;
    const float* xr = x + j * FIN;
    float acc = 0.f;
#pragma unroll
    for (int f = 0; f < FIN; f++) acc += xr[f] * sWA[f * 96 + c];
    d_scratch[OFF_A1 + idx] = acc;
}

// edge pass 1: 4 threads per edge, 4 channels each (16 ch gcn + 16 ch ecc)
__global__ void pass1_kernel(const int* __restrict__ ei,
                             const float* __restrict__ av,
                             const float* __restrict__ ef) {
    int t = blockIdx.x * blockDim.x + threadIdx.x;
    int edge = t >> 2, q = t & 3;
    if (edge >= EE) return;
    int row = ei[edge];
    int col = ei[EE + edge];
    float a  = av[edge];
    float e0 = ef[edge * 3 + 0], e1 = ef[edge * 3 + 1], e2 = ef[edge * 3 + 2];
    const float4* A = (const float4*)(d_scratch + OFF_A1 + col * 96);
    float4 h  = A[q];
    float4 u0 = A[4 + q], u1 = A[8 + q], u2 = A[12 + q], vb = A[16 + q];
    float4 gm = make_float4(a * h.x, a * h.y, a * h.z, a * h.w);
    float4 cm = make_float4(e0 * u0.x + e1 * u1.x + e2 * u2.x + vb.x,
                            e0 * u0.y + e1 * u1.y + e2 * u2.y + vb.y,
                            e0 * u0.z + e1 * u1.z + e2 * u2.z + vb.z,
                            e0 * u0.w + e1 * u1.w + e2 * u2.w + vb.w);
    red_add_v4(d_scratch + OFF_AG1 + row * 16 + q * 4, gm);
    red_add_v4(d_scratch + OFF_AC1 + row * 16 + q * 4, cm);
}

// relu layer-1 accums, then fused GEMMs:
//   g1[16] -> H2[32] via W_gcn2 ; c1[16] -> (U2|V2|xr2)[160] via WC
__global__ void stageC_kernel(const float* __restrict__ Wg2,
                              const float* __restrict__ bg1,
                              const float* __restrict__ bias1) {
    __shared__ float sW2[512];
    __shared__ float sWC[2560];
    __shared__ float sIn[8][32];
    for (int i = threadIdx.x; i < 512;  i += blockDim.x) sW2[i] = Wg2[i];
    for (int i = threadIdx.x; i < 2560; i += blockDim.x) sWC[i] = d_scratch[OFF_WC + i];
    __syncthreads();
    int w = threadIdx.x >> 5, lane = threadIdx.x & 31;
    int node = blockIdx.x * 8 + w;
    if (node >= NN) return;
    float val;
    if (lane < 16) {
        val = fmaxf(d_scratch[OFF_AG1 + node * 16 + lane] + bg1[lane], 0.f);
    } else {
        int f = lane - 16;
        val = fmaxf(d_scratch[OFF_AC1 + node * 16 + f]
                    + d_scratch[OFF_A1 + node * 96 + 80 + f] + bias1[f], 0.f);
    }
    sIn[w][lane] = val;
    __syncwarp();
#pragma unroll
    for (int k = 0; k < 6; k++) {
        int o = lane + 32 * k;
        float acc = 0.f;
        if (o < 32) {
#pragma unroll
            for (int f = 0; f < 16; f++) acc += sIn[w][f] * sW2[f * 32 + o];
            d_scratch[OFF_H2 + node * 32 + o] = acc;
        } else {
            int c = o - 32;
#pragma unroll
            for (int f = 0; f < 16; f++) acc += sIn[w][16 + f] * sWC[f * 160 + c];
            if (c < 128) d_scratch[OFF_UV2 + node * 128 + c] = acc;
            else         d_scratch[OFF_XR2 + node * 32 + (c - 128)] = acc;
        }
    }
}

// edge pass 2: 8 threads per edge, 4 channels each (32 ch gcn + 32 ch ecc)
__global__ void pass2_kernel(const int* __restrict__ ei,
                             const float* __restrict__ av,
                             const float* __restrict__ ef) {
    int t = blockIdx.x * blockDim.x + threadIdx.x;
    int edge = t >> 3, q = t & 7;
    if (edge >= EE) return;
    int row = ei[edge];
    int col = ei[EE + edge];
    float a  = av[edge];
    float e0 = ef[edge * 3 + 0], e1 = ef[edge * 3 + 1], e2 = ef[edge * 3 + 2];
    const float4* U = (const float4*)(d_scratch + OFF_UV2 + col * 128);
    float4 u0 = U[q], u1 = U[8 + q], u2 = U[16 + q], vb = U[24 + q];
    float4 h  = ((const float4*)(d_scratch + OFF_H2 + col * 32))[q];
    float4 gm = make_float4(a * h.x, a * h.y, a * h.z, a * h.w);
    float4 cm = make_float4(e0 * u0.x + e1 * u1.x + e2 * u2.x + vb.x,
                            e0 * u0.y + e1 * u1.y + e2 * u2.y + vb.y,
                            e0 * u0.z + e1 * u1.z + e2 * u2.z + vb.z,
                            e0 * u0.w + e1 * u1.w + e2 * u2.w + vb.w);
    red_add_v4(d_scratch + OFF_AG2 + row * 32 + q * 4, gm);
    red_add_v4(d_scratch + OFF_AC2 + row * 32 + q * 4, cm);
}

// relu layer-2 accums + bias, pool per-graph into POOL[G,64] = [p1(32) | p2(32)]
__global__ void stageE_kernel(const int* __restrict__ seg,
                              const float* __restrict__ bg2,
                              const float* __restrict__ bias2) {
    int t = blockIdx.x * blockDim.x + threadIdx.x;
    int node = t >> 4, q = t & 15;
    if (node >= NN) return;
    int g = seg[node];
    if (q < 8) {
        int ch = q * 4;
        float4 v = *(const float4*)(d_scratch + OFF_AG2 + node * 32 + ch);
        v.x += bg2[ch];     v.y += bg2[ch + 1];
        v.z += bg2[ch + 2]; v.w += bg2[ch + 3];
        v = relu4(v);
        red_add_v4(d_scratch + OFF_POOL + g * 64 + ch, v);
    } else {
        int ch = (q - 8) * 4;
        float4 v = *(const float4*)(d_scratch + OFF_AC2 + node * 32 + ch);
        float4 xr = *(const float4*)(d_scratch + OFF_XR2 + node * 32 + ch);
        v.x += xr.x + bias2[ch];     v.y += xr.y + bias2[ch + 1];
        v.z += xr.z + bias2[ch + 2]; v.w += xr.w + bias2[ch + 3];
        v = relu4(v);
        red_add_v4(d_scratch + OFF_POOL + g * 64 + 32 + ch, v);
    }
}

// MLP head: [G,64] -> 16 -> 8 -> sigmoid -> out[G]
__global__ void head_kernel(const float* __restrict__ Wd1, const float* __restrict__ bd1,
                            const float* __restrict__ Wd2, const float* __restrict__ bd2,
                            const float* __restrict__ Wo,  const float* __restrict__ bo,
                            float* __restrict__ out) {
    __shared__ float sW1[64 * 16];
    __shared__ float sb1[16];
    __shared__ float sW2[16 * 8];
    __shared__ float sb2[8];
    __shared__ float sWo[8];
    for (int i = threadIdx.x; i < 1024; i += blockDim.x) sW1[i] = Wd1[i];
    if (threadIdx.x < 16)  sb1[threadIdx.x] = bd1[threadIdx.x];
    if (threadIdx.x < 128) sW2[threadIdx.x] = Wd2[threadIdx.x];
    if (threadIdx.x < 8)   { sb2[threadIdx.x] = bd2[threadIdx.x]; sWo[threadIdx.x] = Wo[threadIdx.x]; }
    __syncthreads();
    int g = blockIdx.x * blockDim.x + threadIdx.x;
    if (g >= GG) return;
    const float* pr = d_scratch + OFF_POOL + g * 64;
    float h1[16];
#pragma unroll
    for (int k = 0; k < 16; k++) h1[k] = sb1[k];
    for (int f = 0; f < 64; f++) {
        float v = pr[f];
#pragma unroll
        for (int k = 0; k < 16; k++) h1[k] += v * sW1[f * 16 + k];
    }
#pragma unroll
    for (int k = 0; k < 16; k++) h1[k] = fmaxf(h1[k], 0.f);
    float h2[8];
#pragma unroll
    for (int m = 0; m < 8; m++) h2[m] = sb2[m];
#pragma unroll
    for (int k = 0; k < 16; k++) {
        float v = h1[k];
#pragma unroll
        for (int m = 0; m < 8; m++) h2[m] += v * sW2[k * 8 + m];
    }
    float z = bo[0];
#pragma unroll
    for (int m = 0; m < 8; m++) z += fmaxf(h2[m], 0.f) * sWo[m];
    out[g] = 1.f / (1.f + expf(-z));
}

// ---------------- launch ----------------
extern "C" void kernel_launch(void* const* d_in, const int* in_sizes, int n_in,
                              void* d_out, int out_size) {
    const float* x     = (const float*)d_in[0];
    const float* av    = (const float*)d_in[1];
    const float* ef    = (const float*)d_in[2];
    const int*   ei    = (const int*)  d_in[3];
    const int*   seg   = (const int*)  d_in[4];
    const float* Wg1   = (const float*)d_in[5];
    const float* bg1   = (const float*)d_in[6];
    const float* Wg2   = (const float*)d_in[7];
    const float* bg2   = (const float*)d_in[8];
    const float* We1   = (const float*)d_in[9];
    const float* be1   = (const float*)d_in[10];
    const float* root1 = (const float*)d_in[11];
    const float* bias1 = (const float*)d_in[12];
    const float* We2   = (const float*)d_in[13];
    const float* be2   = (const float*)d_in[14];
    const float* root2 = (const float*)d_in[15];
    const float* bias2 = (const float*)d_in[16];
    const float* Wd1   = (const float*)d_in[17];
    const float* bd1   = (const float*)d_in[18];
    const float* Wd2   = (const float*)d_in[19];
    const float* bd2   = (const float*)d_in[20];
    const float* Wo    = (const float*)d_in[21];
    const float* bo    = (const float*)d_in[22];
    float* out = (float*)d_out;

    zero_kernel<<<(ZERO_COUNT / 4 + 255) / 256, 256>>>();
    prep_kernel<<<14, 256>>>(Wg1, We1, be1, root1, We2, be2, root2);
    stageA_kernel<<<(NN * 96 + 255) / 256, 256>>>(x);
    pass1_kernel<<<(EE * 4 + 255) / 256, 256>>>(ei, av, ef);
    stageC_kernel<<<NN / 8, 256>>>(Wg2, bg1, bias1);
    pass2_kernel<<<(EE * 8 + 255) / 256, 256>>>(ei, av, ef);
    stageE_kernel<<<(NN * 16 + 255) / 256, 256>>>(seg, bg2, bias2);
    head_kernel<<<2, 256>>>(Wd1, bd1, Wd2, bd2, Wo, bo, out);
}

// round 3
// speedup vs baseline: 1.2656x; 1.2656x over previous
#include <cuda_runtime.h>

#define NN 60000
#define EE 240000
#define GG 512

// ---------------- scratch layout (floats) ----------------
// X12  : N*12  (x padded to 12 features)
// G1   : N*16  (gcn layer-1 output)
// C1   : N*16  (ecc layer-1 output)
// -- zeroed region --
// AGG1 : N*64  ([a*x | e0*x | e1*x | e2*x | 1*x] each 12-wide, +4 pad)
// AGG2 : N*80  ([a*g1 16 | e0*c1 | e1*c1 | e2*c1 | 1*c1 each 16])
// POOL : G*64  ([g2 pooled 32 | c2 pooled 32])
constexpr int OFF_X12  = 0;
constexpr int OFF_G1   = OFF_X12 + NN * 12;
constexpr int OFF_C1   = OFF_G1  + NN * 16;
constexpr int OFF_ZERO = OFF_C1  + NN * 16;
constexpr int OFF_AGG1 = OFF_ZERO;
constexpr int OFF_AGG2 = OFF_AGG1 + NN * 64;
constexpr int OFF_POOL = OFF_AGG2 + NN * 80;
constexpr int SCRATCH_TOTAL = OFF_POOL + GG * 64;
constexpr int ZERO_COUNT = SCRATCH_TOTAL - OFF_ZERO;

__device__ __align__(16) float d_scratch[SCRATCH_TOTAL];

// ---------------- helpers ----------------
__device__ __forceinline__ void red_add_v4(float* addr, float4 v) {
    asm volatile("red.global.add.v4.f32 [%0], {%1, %2, %3, %4};"
                 :: "l"(addr), "f"(v.x), "f"(v.y), "f"(v.z), "f"(v.w)
                 : "memory");
}

typedef unsigned long long ull;

__device__ __forceinline__ ull pk2(float lo, float hi) {
    ull r;
    asm("mov.b64 %0, {%1, %2};" : "=l"(r) : "f"(lo), "f"(hi));
    return r;
}
__device__ __forceinline__ void fma2(ull& acc, ull a, ull b) {
    asm("fma.rn.f32x2 %0, %1, %2, %0;" : "+l"(acc) : "l"(a), "l"(b));
}
__device__ __forceinline__ float2 upk(ull v) {
    float2 o;
    asm("mov.b64 {%0, %1}, %2;" : "=f"(o.x), "=f"(o.y) : "l"(v));
    return o;
}

// ---------------- kernels ----------------
// zero accumulators + build padded X12
__global__ void init_kernel(const float* __restrict__ x) {
    int i = blockIdx.x * blockDim.x + threadIdx.x;
    constexpr int ZC4 = ZERO_COUNT / 4;
    if (i < ZC4) {
        ((float4*)(d_scratch + OFF_ZERO))[i] = make_float4(0.f, 0.f, 0.f, 0.f);
        return;
    }
    int j = i - ZC4;
    if (j < NN * 3) {
        int node = j / 3, p = j - node * 3;
        int f0 = p * 4;
        const float* xr = x + node * 10;
        float4 v;
        v.x = (f0 + 0 < 10) ? xr[f0 + 0] : 0.f;
        v.y = (f0 + 1 < 10) ? xr[f0 + 1] : 0.f;
        v.z = (f0 + 2 < 10) ? xr[f0 + 2] : 0.f;
        v.w = (f0 + 3 < 10) ? xr[f0 + 3] : 0.f;
        ((float4*)(d_scratch + OFF_X12))[node * 3 + p] = v;
    }
}

// pass1: 5 threads/edge, each applies one coefficient (a, e0, e1, e2, 1) to x12[col]
__global__ void pass1_kernel(const int* __restrict__ ei,
                             const float* __restrict__ av,
                             const float* __restrict__ ef) {
    int t = blockIdx.x * blockDim.x + threadIdx.x;
    int edge = t / 5;
    int q = t - edge * 5;
    if (edge >= EE) return;
    int row = ei[edge];
    int col = ei[EE + edge];
    float coeff;
    if (q == 0)      coeff = av[edge];
    else if (q < 4)  coeff = ef[edge * 3 + (q - 1)];
    else             coeff = 1.f;
    const float4* xp = (const float4*)(d_scratch + OFF_X12 + col * 12);
    float* dst = d_scratch + OFF_AGG1 + row * 64 + q * 12;
#pragma unroll
    for (int k = 0; k < 3; k++) {
        float4 v = xp[k];
        red_add_v4(dst + k * 4,
                   make_float4(coeff * v.x, coeff * v.y, coeff * v.z, coeff * v.w));
    }
}

// post1: per-node contractions -> g1[16], c1[16]
__global__ void post1_kernel(const float* __restrict__ Wg1, const float* __restrict__ bg1,
                             const float* __restrict__ We1, const float* __restrict__ be1,
                             const float* __restrict__ root1, const float* __restrict__ bias1) {
    __shared__ __align__(16) float sWg1[160];
    __shared__ __align__(16) float sK1[640];   // [s=0..3][f<10][o<16]; s<3: We1, s=3: be1
    __shared__ __align__(16) float sR1[160];
    __shared__ float sBg[16], sB1[16];
    int tid = threadIdx.x;
    for (int i = tid; i < 160; i += blockDim.x) { sWg1[i] = Wg1[i]; sR1[i] = root1[i]; }
    for (int i = tid; i < 640; i += blockDim.x) sK1[i] = (i < 480) ? We1[i] : be1[i - 480];
    if (tid < 16) { sBg[tid] = bg1[tid]; sB1[tid] = bias1[tid]; }
    __syncthreads();
    int node = blockIdx.x * blockDim.x + tid;
    if (node >= NN) return;

    ull ga[8], ca[8];
#pragma unroll
    for (int k = 0; k < 8; k++) {
        ga[k] = pk2(sBg[2 * k], sBg[2 * k + 1]);
        ca[k] = pk2(sB1[2 * k], sB1[2 * k + 1]);
    }
    const float4* ap = (const float4*)(d_scratch + OFF_AGG1 + node * 64);

    // gcn part: channels 0..9 (a-weighted x), chunks 0..2
#pragma unroll
    for (int c4 = 0; c4 < 3; c4++) {
        float4 v = ap[c4];
        float vv[4] = {v.x, v.y, v.z, v.w};
#pragma unroll
        for (int j = 0; j < 4; j++) {
            int f = c4 * 4 + j;
            if (f < 10) {
                ull s = pk2(vv[j], vv[j]);
                const ulonglong2* w = (const ulonglong2*)&sWg1[f * 16];
#pragma unroll
                for (int k = 0; k < 4; k++) {
                    ulonglong2 wp = w[k];
                    fma2(ga[2 * k], s, wp.x);
                    fma2(ga[2 * k + 1], s, wp.y);
                }
            }
        }
    }
    // ecc aggregated part: channels 12..59 -> (s_i, f), chunks 3..14
#pragma unroll
    for (int c4 = 3; c4 < 15; c4++) {
        float4 v = ap[c4];
        float vv[4] = {v.x, v.y, v.z, v.w};
#pragma unroll
        for (int j = 0; j < 4; j++) {
            int fi = c4 * 4 + j - 12;
            int s_i = fi / 12, f = fi - s_i * 12;
            if (f < 10) {
                ull s = pk2(vv[j], vv[j]);
                const ulonglong2* w = (const ulonglong2*)&sK1[s_i * 160 + f * 16];
#pragma unroll
                for (int k = 0; k < 4; k++) {
                    ulonglong2 wp = w[k];
                    fma2(ca[2 * k], s, wp.x);
                    fma2(ca[2 * k + 1], s, wp.y);
                }
            }
        }
    }
    // root term: x12 itself
    const float4* xp = (const float4*)(d_scratch + OFF_X12 + node * 12);
#pragma unroll
    for (int c4 = 0; c4 < 3; c4++) {
        float4 v = xp[c4];
        float vv[4] = {v.x, v.y, v.z, v.w};
#pragma unroll
        for (int j = 0; j < 4; j++) {
            int f = c4 * 4 + j;
            if (f < 10) {
                ull s = pk2(vv[j], vv[j]);
                const ulonglong2* w = (const ulonglong2*)&sR1[f * 16];
#pragma unroll
                for (int k = 0; k < 4; k++) {
                    ulonglong2 wp = w[k];
                    fma2(ca[2 * k], s, wp.x);
                    fma2(ca[2 * k + 1], s, wp.y);
                }
            }
        }
    }
    // relu + store
    float4* g1o = (float4*)(d_scratch + OFF_G1 + node * 16);
    float4* c1o = (float4*)(d_scratch + OFF_C1 + node * 16);
#pragma unroll
    for (int k = 0; k < 4; k++) {
        float2 a0 = upk(ga[2 * k]), a1 = upk(ga[2 * k + 1]);
        g1o[k] = make_float4(fmaxf(a0.x, 0.f), fmaxf(a0.y, 0.f),
                             fmaxf(a1.x, 0.f), fmaxf(a1.y, 0.f));
        float2 b0 = upk(ca[2 * k]), b1 = upk(ca[2 * k + 1]);
        c1o[k] = make_float4(fmaxf(b0.x, 0.f), fmaxf(b0.y, 0.f),
                             fmaxf(b1.x, 0.f), fmaxf(b1.y, 0.f));
    }
}

// pass2: 4 threads/edge, each handles a 4-feature slice of g1/c1
__global__ void pass2_kernel(const int* __restrict__ ei,
                             const float* __restrict__ av,
                             const float* __restrict__ ef) {
    int t = blockIdx.x * blockDim.x + threadIdx.x;
    int edge = t >> 2, q = t & 3;
    if (edge >= EE) return;
    int row = ei[edge];
    int col = ei[EE + edge];
    float a  = av[edge];
    float e0 = ef[edge * 3 + 0], e1 = ef[edge * 3 + 1], e2 = ef[edge * 3 + 2];
    float4 g1v = ((const float4*)(d_scratch + OFF_G1 + col * 16))[q];
    float4 c1v = ((const float4*)(d_scratch + OFF_C1 + col * 16))[q];
    float* base = d_scratch + OFF_AGG2 + row * 80;
    red_add_v4(base + q * 4, make_float4(a * g1v.x, a * g1v.y, a * g1v.z, a * g1v.w));
    float coeffs[4] = {e0, e1, e2, 1.f};
#pragma unroll
    for (int s = 0; s < 4; s++) {
        float c = coeffs[s];
        red_add_v4(base + 16 + s * 16 + q * 4,
                   make_float4(c * c1v.x, c * c1v.y, c * c1v.z, c * c1v.w));
    }
}

// post2: per-node contractions -> g2[32], c2[32], relu, per-graph pool via REDs
__global__ void post2_kernel(const int* __restrict__ seg,
                             const float* __restrict__ Wg2, const float* __restrict__ bg2,
                             const float* __restrict__ We2, const float* __restrict__ be2,
                             const float* __restrict__ root2, const float* __restrict__ bias2) {
    __shared__ __align__(16) float sWg2[512];
    __shared__ __align__(16) float sK2[2048];  // [s][f<16][o<32]; s<3: We2, s=3: be2
    __shared__ __align__(16) float sR2[512];
    __shared__ float sBg[32], sB2[32];
    int tid = threadIdx.x;
    for (int i = tid; i < 512; i += blockDim.x) { sWg2[i] = Wg2[i]; sR2[i] = root2[i]; }
    for (int i = tid; i < 2048; i += blockDim.x) sK2[i] = (i < 1536) ? We2[i] : be2[i - 1536];
    if (tid < 32) { sBg[tid] = bg2[tid]; sB2[tid] = bias2[tid]; }
    __syncthreads();
    int node = blockIdx.x * blockDim.x + tid;
    if (node >= NN) return;

    ull ga[16], ca[16];
#pragma unroll
    for (int k = 0; k < 16; k++) {
        ga[k] = pk2(sBg[2 * k], sBg[2 * k + 1]);
        ca[k] = pk2(sB2[2 * k], sB2[2 * k + 1]);
    }
    const float4* ap = (const float4*)(d_scratch + OFF_AGG2 + node * 80);

    // g2: inputs agg[0..15]
#pragma unroll
    for (int c4 = 0; c4 < 4; c4++) {
        float4 v = ap[c4];
        float vv[4] = {v.x, v.y, v.z, v.w};
#pragma unroll
        for (int j = 0; j < 4; j++) {
            int f = c4 * 4 + j;
            ull s = pk2(vv[j], vv[j]);
            const ulonglong2* w = (const ulonglong2*)&sWg2[f * 32];
#pragma unroll
            for (int k = 0; k < 8; k++) {
                ulonglong2 wp = w[k];
                fma2(ga[2 * k], s, wp.x);
                fma2(ga[2 * k + 1], s, wp.y);
            }
        }
    }
    // c2: inputs agg[16..79] -> (s_i, f)
#pragma unroll
    for (int c4 = 4; c4 < 20; c4++) {
        float4 v = ap[c4];
        float vv[4] = {v.x, v.y, v.z, v.w};
#pragma unroll
        for (int j = 0; j < 4; j++) {
            int fi = (c4 - 4) * 4 + j;
            int s_i = fi >> 4, f = fi & 15;
            ull s = pk2(vv[j], vv[j]);
            const ulonglong2* w = (const ulonglong2*)&sK2[s_i * 512 + f * 32];
#pragma unroll
            for (int k = 0; k < 8; k++) {
                ulonglong2 wp = w[k];
                fma2(ca[2 * k], s, wp.x);
                fma2(ca[2 * k + 1], s, wp.y);
            }
        }
    }
    // root term: c1
    const float4* cp = (const float4*)(d_scratch + OFF_C1 + node * 16);
#pragma unroll
    for (int c4 = 0; c4 < 4; c4++) {
        float4 v = cp[c4];
        float vv[4] = {v.x, v.y, v.z, v.w};
#pragma unroll
        for (int j = 0; j < 4; j++) {
            int f = c4 * 4 + j;
            ull s = pk2(vv[j], vv[j]);
            const ulonglong2* w = (const ulonglong2*)&sR2[f * 32];
#pragma unroll
            for (int k = 0; k < 8; k++) {
                ulonglong2 wp = w[k];
                fma2(ca[2 * k], s, wp.x);
                fma2(ca[2 * k + 1], s, wp.y);
            }
        }
    }
    // relu + pool into POOL[g][0..31]=g2, [32..63]=c2
    int g = seg[node];
    float* pb = d_scratch + OFF_POOL + g * 64;
#pragma unroll
    for (int k = 0; k < 8; k++) {
        float2 a0 = upk(ga[2 * k]), a1 = upk(ga[2 * k + 1]);
        red_add_v4(pb + k * 4,
                   make_float4(fmaxf(a0.x, 0.f), fmaxf(a0.y, 0.f),
                               fmaxf(a1.x, 0.f), fmaxf(a1.y, 0.f)));
        float2 b0 = upk(ca[2 * k]), b1 = upk(ca[2 * k + 1]);
        red_add_v4(pb + 32 + k * 4,
                   make_float4(fmaxf(b0.x, 0.f), fmaxf(b0.y, 0.f),
                               fmaxf(b1.x, 0.f), fmaxf(b1.y, 0.f)));
    }
}

// MLP head: [G,64] -> 16 -> 8 -> sigmoid -> out[G]
__global__ void head_kernel(const float* __restrict__ Wd1, const float* __restrict__ bd1,
                            const float* __restrict__ Wd2, const float* __restrict__ bd2,
                            const float* __restrict__ Wo,  const float* __restrict__ bo,
                            float* __restrict__ out) {
    __shared__ float sW1[64 * 16];
    __shared__ float sb1[16];
    __shared__ float sW2[16 * 8];
    __shared__ float sb2[8];
    __shared__ float sWo[8];
    for (int i = threadIdx.x; i < 1024; i += blockDim.x) sW1[i] = Wd1[i];
    if (threadIdx.x < 16)  sb1[threadIdx.x] = bd1[threadIdx.x];
    if (threadIdx.x < 128) sW2[threadIdx.x] = Wd2[threadIdx.x];
    if (threadIdx.x < 8)   { sb2[threadIdx.x] = bd2[threadIdx.x]; sWo[threadIdx.x] = Wo[threadIdx.x]; }
    __syncthreads();
    int g = blockIdx.x * blockDim.x + threadIdx.x;
    if (g >= GG) return;
    const float* pr = d_scratch + OFF_POOL + g * 64;
    float h1[16];
#pragma unroll
    for (int k = 0; k < 16; k++) h1[k] = sb1[k];
    for (int f = 0; f < 64; f++) {
        float v = pr[f];
#pragma unroll
        for (int k = 0; k < 16; k++) h1[k] += v * sW1[f * 16 + k];
    }
#pragma unroll
    for (int k = 0; k < 16; k++) h1[k] = fmaxf(h1[k], 0.f);
    float h2[8];
#pragma unroll
    for (int m = 0; m < 8; m++) h2[m] = sb2[m];
#pragma unroll
    for (int k = 0; k < 16; k++) {
        float v = h1[k];
#pragma unroll
        for (int m = 0; m < 8; m++) h2[m] += v * sW2[k * 8 + m];
    }
    float z = bo[0];
#pragma unroll
    for (int m = 0; m < 8; m++) z += fmaxf(h2[m], 0.f) * sWo[m];
    out[g] = 1.f / (1.f + expf(-z));
}

// ---------------- launch ----------------
extern "C" void kernel_launch(void* const* d_in, const int* in_sizes, int n_in,
                              void* d_out, int out_size) {
    const float* x     = (const float*)d_in[0];
    const float* av    = (const float*)d_in[1];
    const float* ef    = (const float*)d_in[2];
    const int*   ei    = (const int*)  d_in[3];
    const int*   seg   = (const int*)  d_in[4];
    const float* Wg1   = (const float*)d_in[5];
    const float* bg1   = (const float*)d_in[6];
    const float* Wg2   = (const float*)d_in[7];
    const float* bg2   = (const float*)d_in[8];
    const float* We1   = (const float*)d_in[9];
    const float* be1   = (const float*)d_in[10];
    const float* root1 = (const float*)d_in[11];
    const float* bias1 = (const float*)d_in[12];
    const float* We2   = (const float*)d_in[13];
    const float* be2   = (const float*)d_in[14];
    const float* root2 = (const float*)d_in[15];
    const float* bias2 = (const float*)d_in[16];
    const float* Wd1   = (const float*)d_in[17];
    const float* bd1   = (const float*)d_in[18];
    const float* Wd2   = (const float*)d_in[19];
    const float* bd2   = (const float*)d_in[20];
    const float* Wo    = (const float*)d_in[21];
    const float* bo    = (const float*)d_in[22];
    float* out = (float*)d_out;

    constexpr int INIT_ITEMS = ZERO_COUNT / 4 + NN * 3;
    init_kernel<<<(INIT_ITEMS + 255) / 256, 256>>>(x);
    pass1_kernel<<<(EE * 5 + 319) / 320, 320>>>(ei, av, ef);
    post1_kernel<<<(NN + 127) / 128, 128>>>(Wg1, bg1, We1, be1, root1, bias1);
    pass2_kernel<<<(EE * 4 + 255) / 256, 256>>>(ei, av, ef);
    post2_kernel<<<(NN + 127) / 128, 128>>>(seg, Wg2, bg2, We2, be2, root2, bias2);
    head_kernel<<<2, 256>>>(Wd1, bd1, Wd2, bd2, Wo, bo, out);
}